// round 17
// baseline (speedup 1.0000x reference)
#include <cuda_runtime.h>
#include <float.h>

// Scratch accumulators — zero-initialized at module load, re-zeroed by
// finalize_kernel every invocation so each graph replay starts clean.
__device__ float        g_sum[4096 * 128];     // segment sums
__device__ unsigned int g_maxk[4096 * 128];    // order-preserving max keys; 0 == -inf
__device__ int          g_counts[4096];        // contributions landed so far

// Order-preserving float<->uint key. Monotone: f1 < f2 <=> key(f1) < key(f2).
// key(x) >= 1 for all finite x, so a zero key acts as -infinity.
__device__ __forceinline__ unsigned int fkey(float f) {
    unsigned int b = __float_as_uint(f);
    return (b & 0x80000000u) ? ~b : (b | 0x80000000u);
}
__device__ __forceinline__ float funkey(unsigned int k) {
    return __uint_as_float((k & 0x80000000u) ? (k & 0x7FFFFFFFu) : ~k);
}

struct Acc {
    float4 s, m;
    int cnt, cur;
};

__device__ __forceinline__ void flush_acc(const Acc& a, int lane, int B) {
    int cc = min(max(a.cur, 0), B - 1);
    float* sb = g_sum + cc * 128 + lane * 4;
    atomicAdd(sb + 0, a.s.x);
    atomicAdd(sb + 1, a.s.y);
    atomicAdd(sb + 2, a.s.z);
    atomicAdd(sb + 3, a.s.w);
    unsigned int* mb = g_maxk + cc * 128 + lane * 4;
    atomicMax(mb + 0, fkey(a.m.x));
    atomicMax(mb + 1, fkey(a.m.y));
    atomicMax(mb + 2, fkey(a.m.z));
    atomicMax(mb + 3, fkey(a.m.w));
    // Release: value atomics visible before the count contribution lands, so
    // a finalize warp observing count==total may safely read the values.
    __threadfence();
    __syncwarp();
    if (lane == 0) atomicAdd(&g_counts[cc], a.cnt);
}

__device__ __forceinline__ void step_acc(Acc& a, int b, float4 v,
                                         int lane, int B) {
    if (b != a.cur) {
        flush_acc(a, lane, B);
        a.s = make_float4(0.f, 0.f, 0.f, 0.f);
        a.m = make_float4(-FLT_MAX, -FLT_MAX, -FLT_MAX, -FLT_MAX);
        a.cnt = 0;
        a.cur = b;
    }
    a.s.x += v.x; a.s.y += v.y; a.s.z += v.z; a.s.w += v.w;
    a.m.x = fmaxf(a.m.x, v.x);
    a.m.y = fmaxf(a.m.y, v.y);
    a.m.z = fmaxf(a.m.z, v.z);
    a.m.w = fmaxf(a.m.w, v.w);
    a.cnt++;
}

// One warp per contiguous row range (4-row aligned). Lanes each own a float4
// (4 features) of the 128-wide row. Rows processed in chunks of 4 with all
// loads issued up-front to hide the ~577-cyc DRAM latency. Accumulate
// sum/max/count in registers; flush to scratch atomically on segment change.
// (R8 hot kernel + one release fence in the cold flush branch.)
__global__ void __launch_bounds__(256) agg_kernel(
    const float4* __restrict__ x,       // [N, 32] float4 view of [N, 128]
    const int* __restrict__ batch,      // [N] sorted segment ids (int32)
    int N, int B)
{
    int gtid   = blockIdx.x * blockDim.x + threadIdx.x;
    int warp   = gtid >> 5;
    int lane   = gtid & 31;
    int nwarps = (gridDim.x * blockDim.x) >> 5;

    // 4-row-aligned contiguous ranges (keeps int4 batch loads aligned).
    long long start = (((long long)N * warp / nwarps) + 3) & ~3LL;
    long long end   = (((long long)N * (warp + 1) / nwarps) + 3) & ~3LL;
    if (end > N) end = N;
    if (start >= end) return;

    Acc a;
    a.s = make_float4(0.f, 0.f, 0.f, 0.f);
    a.m = make_float4(-FLT_MAX, -FLT_MAX, -FLT_MAX, -FLT_MAX);
    a.cnt = 0;
    a.cur = __ldcs(&batch[start]);

    long long r = start;
    for (; r + 4 <= end; r += 4) {
        int4 b4 = __ldcs((const int4*)&batch[r]);
        float4 v0 = __ldcs(&x[(r + 0) * 32 + lane]);
        float4 v1 = __ldcs(&x[(r + 1) * 32 + lane]);
        float4 v2 = __ldcs(&x[(r + 2) * 32 + lane]);
        float4 v3 = __ldcs(&x[(r + 3) * 32 + lane]);
        step_acc(a, b4.x, v0, lane, B);
        step_acc(a, b4.y, v1, lane, B);
        step_acc(a, b4.z, v2, lane, B);
        step_acc(a, b4.w, v3, lane, B);
    }
    for (; r < end; ++r) {
        int b = __ldcs(&batch[r]);
        float4 v = __ldcs(&x[r * 32 + lane]);
        step_acc(a, b, v, lane, B);
    }

    flush_acc(a, lane, B);
}

// Per-segment overlapped finalize. One warp per segment (lane == float4
// group). Launched with PDL (no grid sync): warps spin until their segment's
// contribution count reaches the true row count (binary search on sorted
// batch), then finalize immediately — overlapping with the agg drain.
// PDL guarantees every agg CTA launches before any finalize CTA: no deadlock.
__global__ void __launch_bounds__(256) finalize_kernel(
    float* __restrict__ out, const int* __restrict__ batch, int N, int B)
{
    int gtid = blockIdx.x * blockDim.x + threadIdx.x;
    int b    = gtid >> 5;          // segment (one warp each)
    int lane = gtid & 31;          // float4 group within 128 features
    if (b >= B) return;

    // Segment extent via binary search (all lanes same path -> broadcast).
    int lo = 0, hi = N;
    while (lo < hi) {              // lower_bound(b)
        int mid = (lo + hi) >> 1;
        if (__ldg(&batch[mid]) < b) lo = mid + 1; else hi = mid;
    }
    int lower = lo;
    hi = N;
    while (lo < hi) {              // upper_bound(b)
        int mid = (lo + hi) >> 1;
        if (__ldg(&batch[mid]) <= b) lo = mid + 1; else hi = mid;
    }
    int total = lo - lower;

    // Wait until all contributions for this segment have landed.
    if (lane == 0) {
        while (((volatile int*)g_counts)[b] < total) __nanosleep(64);
    }
    __syncwarp();
    __threadfence();               // acquire: see all flushers' value atomics

    int i = b * 32 + lane;
    float4 s = __ldcg(((const float4*)g_sum) + i);
    uint4  k = __ldcg(((const uint4*)g_maxk) + i);

    float inv = 1.0f / fmaxf((float)total, 1.0f);
    float4 mean = make_float4(s.x * inv, s.y * inv, s.z * inv, s.w * inv);
    float4 mx;
    if (total > 0) {
        mx = make_float4(funkey(k.x), funkey(k.y), funkey(k.z), funkey(k.w));
    } else {
        s  = make_float4(0.f, 0.f, 0.f, 0.f);
        mean = s;
        mx = s;
    }

    float4* row = (float4*)(out + (long long)b * 384);
    __stcs(row + lane,      s);
    __stcs(row + 32 + lane, mean);
    __stcs(row + 64 + lane, mx);

    // Reset scratch for the next replay.
    ((float4*)g_sum)[i] = make_float4(0.f, 0.f, 0.f, 0.f);
    ((uint4*)g_maxk)[i] = make_uint4(0u, 0u, 0u, 0u);
    if (lane == 0) g_counts[b] = 0;
}

extern "C" void kernel_launch(void* const* d_in, const int* in_sizes, int n_in,
                              void* d_out, int out_size) {
    const float4* x  = (const float4*)d_in[0];
    const int* batch = (const int*)d_in[1];   // int32 on device (verified)
    float* out       = (float*)d_out;

    int N = in_sizes[1];           // number of rows
    int B = out_size / 384;        // segments (out is [B, 3*128])

    // Main aggregation: 1216 blocks x 256 threads (~7 TB/s).
    agg_kernel<<<1216, 256>>>(x, batch, N, B);

    // Overlapped finalize: one warp per segment, PDL so its CTAs can start
    // on freed SM slots while agg drains; per-segment spin gates correctness.
    {
        int threads = 256;
        int blocks  = (B * 32 + threads - 1) / threads;   // 1 warp / segment
        cudaLaunchConfig_t cfg = {};
        cfg.gridDim  = dim3(blocks, 1, 1);
        cfg.blockDim = dim3(threads, 1, 1);
        cudaLaunchAttribute attr[1];
        attr[0].id = cudaLaunchAttributeProgrammaticStreamSerialization;
        attr[0].val.programmaticStreamSerializationAllowed = 1;
        cfg.attrs    = attr;
        cfg.numAttrs = 1;
        cudaLaunchKernelEx(&cfg, finalize_kernel, out, batch, N, B);
    }
}